// round 15
// baseline (speedup 1.0000x reference)
#include <cuda_runtime.h>
#include <math.h>
#include <stdint.h>

#define B_ 8
#define N_ 16384
#define M_ 512
#define K_ 32
#define C_ 6
#define FPS_P 4096      // points per FPS CTA per batch (4-CTA cluster, 2 batches/cluster)

// -------------------- scratch --------------------
__device__ int    g_center_idx[B_ * M_];
__device__ float  g_centers[B_ * M_ * 3];
__device__ int    g_gidx[B_ * M_ * K_];
__device__ float4 g_xyz[B_ * N_];
__device__ __align__(16) uint32_t g_wf1[2 * 4 * 128];
__device__ __align__(16) uint32_t g_wf2[8 * 8 * 128];
__device__ __align__(16) uint32_t g_wf3[16 * 16 * 128];
__device__ __align__(16) uint32_t g_wf4[32 * 24 * 128];
__device__ float g_ps[448], g_po[448];

// -------------------- helpers --------------------
__device__ __forceinline__ unsigned okey(float f) {
    unsigned u = __float_as_uint(f);
    unsigned mask = (u & 0x80000000u) ? 0xFFFFFFFFu : 0x80000000u;
    return u ^ mask;
}
__device__ __forceinline__ uint32_t f2tf32(float x) {
    uint32_t r;
    asm("cvt.rna.tf32.f32 %0, %1;" : "=r"(r) : "f"(x));
    return r;
}
__device__ __forceinline__ void mma_tf32(float* c, uint32_t a0, uint32_t a1,
                                         uint32_t a2, uint32_t a3,
                                         uint32_t b0, uint32_t b1) {
    asm volatile(
        "mma.sync.aligned.m16n8k8.row.col.f32.tf32.tf32.f32 "
        "{%0,%1,%2,%3}, {%4,%5,%6,%7}, {%8,%9}, {%0,%1,%2,%3};"
        : "+f"(c[0]), "+f"(c[1]), "+f"(c[2]), "+f"(c[3])
        : "r"(a0), "r"(a1), "r"(a2), "r"(a3), "r"(b0), "r"(b1));
}
__device__ __forceinline__ uint32_t smem_u32(const void* p) {
    uint32_t a;
    asm("{ .reg .u64 t; cvta.to.shared.u64 t, %1; cvt.u32.u64 %0, t; }" : "=r"(a) : "l"(p));
    return a;
}
__device__ __forceinline__ uint32_t mapa_sh(uint32_t addr, uint32_t rank) {
    uint32_t r;
    asm("mapa.shared::cluster.u32 %0, %1, %2;" : "=r"(r) : "r"(addr), "r"(rank));
    return r;
}
__device__ __forceinline__ void stsc_u64(uint32_t a, unsigned long long v) {
    asm volatile("st.shared::cluster.b64 [%0], %1;" :: "r"(a), "l"(v) : "memory");
}
__device__ __forceinline__ void stsc_u32(uint32_t a, unsigned v) {
    asm volatile("st.shared::cluster.b32 [%0], %1;" :: "r"(a), "r"(v) : "memory");
}
__device__ __forceinline__ void cluster_sync_() {
    asm volatile("barrier.cluster.arrive.aligned;" ::: "memory");
    asm volatile("barrier.cluster.wait.aligned;" ::: "memory");
}
__device__ __forceinline__ unsigned long long packu64(unsigned lo, unsigned hi) {
    unsigned long long d;
    asm("mov.b64 %0, {%1, %2};" : "=l"(d) : "r"(lo), "r"(hi));
    return d;
}
__device__ __forceinline__ float dist2c(float cx, float cy, float cz, float cc2,
                                        float4 q) {
    float dot = __fmaf_rn(cx, q.x, __fmaf_rn(cy, q.y, __fmul_rn(cz, q.z)));
    return __fadd_rn(__fmaf_rn(-2.0f, dot, cc2), q.w);
}

// -------------------- merged weight-fragment prep --------------------
__device__ __forceinline__ void frag_one(const float* w, uint32_t* dst,
                                         int CIN, int DOUT, int idx) {
    int r = idx & 1, o = (idx >> 1) & 1, lane = (idx >> 2) & 31;
    int rest = idx >> 7;
    int np = DOUT / 16;
    int p = rest % np, kt = rest / np;
    int nt = 2 * p + o;
    int n = nt * 8 + (lane >> 2);
    int k = kt * 8 + (lane & 3) + 4 * r;
    float v = (k < CIN) ? w[(size_t)k * DOUT + n] : 0.0f;
    dst[idx] = f2tf32(v);
}
#define T1 (2 * 4 * 128)
#define T2 (8 * 8 * 128)
#define T3 (16 * 16 * 128)
#define T4 (32 * 24 * 128)
__global__ void prep_frag_all(const float* __restrict__ w1, const float* __restrict__ w2,
                              const float* __restrict__ w3, const float* __restrict__ w4) {
    int idx = blockIdx.x * blockDim.x + threadIdx.x;
    if (idx < T1) { frag_one(w1, g_wf1, 9, 64, idx); return; }
    idx -= T1;
    if (idx < T2) { frag_one(w2, g_wf2, 64, 128, idx); return; }
    idx -= T2;
    if (idx < T3) { frag_one(w3, g_wf3, 128, 256, idx); return; }
    idx -= T3;
    if (idx < T4) { frag_one(w4, g_wf4, 256, 384, idx); }
}

__global__ void prep_p_all(
    const float* __restrict__ b1, const float* __restrict__ g1,
    const float* __restrict__ be1, const float* __restrict__ m1, const float* __restrict__ v1,
    const float* __restrict__ b2, const float* __restrict__ g2,
    const float* __restrict__ be2, const float* __restrict__ m2, const float* __restrict__ v2,
    const float* __restrict__ b3, const float* __restrict__ g3,
    const float* __restrict__ be3, const float* __restrict__ m3, const float* __restrict__ v3)
{
    int i = blockIdx.x * blockDim.x + threadIdx.x;
    if (i >= 448) return;
    const float *b, *g, *be, *m, *v;
    int off;
    if (i < 64)       { b = b1; g = g1; be = be1; m = m1; v = v1; off = i; }
    else if (i < 192) { b = b2; g = g2; be = be2; m = m2; v = v2; off = i - 64; }
    else              { b = b3; g = g3; be = be3; m = m3; v = v3; off = i - 192; }
    float sc = g[off] * rsqrtf(v[off] + 1e-5f);
    g_ps[i] = sc;
    g_po[i] = (b[off] - m[off]) * sc + be[off];
}

// -------------------- pack xyz --------------------
__global__ void pack_kernel(const float* __restrict__ pts) {
    int i = blockIdx.x * blockDim.x + threadIdx.x;
    if (i < B_ * N_) {
        const float* p = pts + (size_t)i * C_;
        float x = p[0], y = p[1], z = p[2];
        g_xyz[i] = make_float4(x, y, z, x * x + y * y + z * z);
    }
}

// -------------------- FPS: 4-CTA cluster, 2 batches per cluster -----------------
// smem floats: sx0[4096] sy0 sz0 sx1 sy1 sz1 (@0..24576) |
//              rk0[32] ri0[32] rk1[32] ri1[32] (u32 @24576) | mail u32[2][2][4][6] @24704
__global__ void __launch_bounds__(1024, 1) __cluster_dims__(4, 1, 1)
fps_kernel(float* centers_out) {
    extern __shared__ float fsm[];
    float* sx0 = fsm;
    float* sy0 = fsm + 4096;
    float* sz0 = fsm + 8192;
    float* sx1 = fsm + 12288;
    float* sy1 = fsm + 16384;
    float* sz1 = fsm + 20480;
    unsigned* rk0 = (unsigned*)(fsm + 24576);
    unsigned* ri0 = rk0 + 32;
    unsigned* rk1 = ri0 + 32;
    unsigned* ri1 = rk1 + 32;
    unsigned* mail = (unsigned*)(fsm + 24704);   // [p][q][rank][6]
    const float* mailf = (const float*)mail;

    const int cl = blockIdx.x >> 2;        // cluster id: batches 2cl, 2cl+1
    const uint32_t rank = blockIdx.x & 3;
    const int b0 = 2 * cl, b1 = 2 * cl + 1;
    const int tid = threadIdx.x;
    const int lane = tid & 31, wid = tid >> 5;
    const uint32_t mail_b = smem_u32(mail);

    float px0[4], py0[4], pz0[4], px1[4], py1[4], pz1[4];
#pragma unroll
    for (int j = 0; j < 4; j++) {
        int n = j * 1024 + tid;
        float4 q0 = g_xyz[b0 * N_ + rank * FPS_P + n];
        float4 q1 = g_xyz[b1 * N_ + rank * FPS_P + n];
        sx0[n] = q0.x; sy0[n] = q0.y; sz0[n] = q0.z;
        sx1[n] = q1.x; sy1[n] = q1.y; sz1[n] = q1.z;
        px0[j] = q0.x; py0[j] = q0.y; pz0[j] = q0.z;
        px1[j] = q1.x; py1[j] = q1.y; pz1[j] = q1.z;
    }
    float dist0[4], dist1[4];
#pragma unroll
    for (int j = 0; j < 4; j++) { dist0[j] = 1e10f; dist1[j] = 1e10f; }
    __syncthreads();

    // initial broadcast (owner rank 0): point 0 coords of each batch -> buffer 1 record 0
    if (rank == 0 && tid == 0) {
        for (uint32_t r = 0; r < 4; r++) {
            uint32_t a0 = mapa_sh(mail_b + 192, r);        // buf1, batch0, rec0
            stsc_u64(a0 + 8, packu64(__float_as_uint(sx0[0]), __float_as_uint(sy0[0])));
            stsc_u32(a0 + 16, __float_as_uint(sz0[0]));
            uint32_t a1 = mapa_sh(mail_b + 192 + 96, r);   // buf1, batch1, rec0
            stsc_u64(a1 + 8, packu64(__float_as_uint(sx1[0]), __float_as_uint(sy1[0])));
            stsc_u32(a1 + 16, __float_as_uint(sz1[0]));
        }
    }
    cluster_sync_();
    int far0 = 0, far1 = 0;
    float cx0 = mailf[48 + 2], cy0 = mailf[48 + 3], cz0 = mailf[48 + 4];
    float cx1 = mailf[48 + 24 + 2], cy1 = mailf[48 + 24 + 3], cz1 = mailf[48 + 24 + 4];

    for (int it = 0; it < M_; ++it) {
        if (rank == 0 && tid == 0) {
            g_center_idx[b0 * M_ + it] = far0;
            g_center_idx[b1 * M_ + it] = far1;
            float* gc0 = g_centers + (size_t)(b0 * M_ + it) * 3;
            gc0[0] = cx0; gc0[1] = cy0; gc0[2] = cz0;
            float* gc1 = g_centers + (size_t)(b1 * M_ + it) * 3;
            gc1[0] = cx1; gc1[1] = cy1; gc1[2] = cz1;
            if (centers_out) {
                float* oc0 = centers_out + (size_t)(b0 * M_ + it) * 3;
                oc0[0] = cx0; oc0[1] = cy0; oc0[2] = cz0;
                float* oc1 = centers_out + (size_t)(b1 * M_ + it) * 3;
                oc1[0] = cx1; oc1[1] = cy1; oc1[2] = cz1;
            }
        }
        float bd0 = -1.0f, bd1 = -1.0f;
        int bi0 = 0x7fffffff, bi1 = 0x7fffffff;
#pragma unroll
        for (int j = 0; j < 4; j++) {
            float dx = px0[j] - cx0, dy = py0[j] - cy0, dz = pz0[j] - cz0;
            float d = dx * dx + dy * dy + dz * dz;
            float nd = fminf(dist0[j], d);
            dist0[j] = nd;
            if (nd > bd0) { bd0 = nd; bi0 = j * 1024 + tid; }
            float ex = px1[j] - cx1, ey = py1[j] - cy1, ez = pz1[j] - cz1;
            float e = ex * ex + ey * ey + ez * ez;
            float ne = fminf(dist1[j], e);
            dist1[j] = ne;
            if (ne > bd1) { bd1 = ne; bi1 = j * 1024 + tid; }
        }
        unsigned key0 = okey(bd0);
        unsigned km0 = __reduce_max_sync(0xffffffffu, key0);
        unsigned im0 = __reduce_min_sync(0xffffffffu,
                           (key0 == km0) ? (unsigned)bi0 : 0xffffffffu);
        unsigned key1 = okey(bd1);
        unsigned km1 = __reduce_max_sync(0xffffffffu, key1);
        unsigned im1 = __reduce_min_sync(0xffffffffu,
                           (key1 == km1) ? (unsigned)bi1 : 0xffffffffu);
        if (lane == 0) {
            rk0[wid] = km0; ri0[wid] = im0;
            rk1[wid] = km1; ri1[wid] = im1;
        }
        __syncthreads();
        const int p = it & 1;
        if (wid < 2) {
            const unsigned* rkq = (wid == 0) ? rk0 : rk1;
            const unsigned* riq = (wid == 0) ? ri0 : ri1;
            const float* sxq = (wid == 0) ? sx0 : sx1;
            const float* syq = (wid == 0) ? sy0 : sy1;
            const float* szq = (wid == 0) ? sz0 : sz1;
            unsigned k2 = rkq[lane], i2 = riq[lane];
            unsigned kmax2 = __reduce_max_sync(0xffffffffu, k2);
            unsigned cnd2 = (k2 == kmax2) ? i2 : 0xffffffffu;
            unsigned imin2 = __reduce_min_sync(0xffffffffu, cnd2);
            if (lane < 4) {   // lanes 0..3 ship this batch's record to rank = lane
                int li = (int)imin2;
                unsigned gi = rank * FPS_P + (unsigned)li;
                float qx = sxq[li], qy = syq[li], qz = szq[li];
                uint32_t a = mapa_sh(mail_b + p * 192 + wid * 96 + rank * 24,
                                     (uint32_t)lane);
                stsc_u64(a, packu64(kmax2, gi));
                stsc_u64(a + 8, packu64(__float_as_uint(qx), __float_as_uint(qy)));
                stsc_u32(a + 16, __float_as_uint(qz));
            }
        }
        cluster_sync_();
        // pick winners for both batches (all threads)
        {
            const unsigned* mb = mail + p * 48;
            unsigned wkey = mb[0]; unsigned wi = mb[1]; int ws = 0;
#pragma unroll
            for (int s = 1; s < 4; s++) {
                unsigned k = mb[s * 6]; unsigned i = mb[s * 6 + 1];
                if (k > wkey || (k == wkey && i < wi)) { wkey = k; wi = i; ws = s; }
            }
            cx0 = __uint_as_float(mb[ws * 6 + 2]);
            cy0 = __uint_as_float(mb[ws * 6 + 3]);
            cz0 = __uint_as_float(mb[ws * 6 + 4]);
            far0 = (int)wi;
        }
        {
            const unsigned* mb = mail + p * 48 + 24;
            unsigned wkey = mb[0]; unsigned wi = mb[1]; int ws = 0;
#pragma unroll
            for (int s = 1; s < 4; s++) {
                unsigned k = mb[s * 6]; unsigned i = mb[s * 6 + 1];
                if (k > wkey || (k == wkey && i < wi)) { wkey = k; wi = i; ws = s; }
            }
            cx1 = __uint_as_float(mb[ws * 6 + 2]);
            cy1 = __uint_as_float(mb[ws * 6 + 3]);
            cz1 = __uint_as_float(mb[ws * 6 + 4]);
            far1 = (int)wi;
        }
    }
}

// -------------------- kNN: 4 centers/CTA, recompute-d2 --------------------
#define KNN_C 4
__global__ void __launch_bounds__(256) knn_kernel() {
    __shared__ int hist[KNN_C * 2048];
    __shared__ int scansm[256];
    __shared__ int selbin[KNN_C], lessc[KNN_C], candc[KNN_C];

    const int bid = blockIdx.x;
    const int gid0 = bid * KNN_C;
    const int b = gid0 >> 9;
    const int tid = threadIdx.x;

    float cx[KNN_C], cy[KNN_C], cz[KNN_C], cc2[KNN_C];
#pragma unroll
    for (int c = 0; c < KNN_C; c++) {
        cx[c] = g_centers[(gid0 + c) * 3 + 0];
        cy[c] = g_centers[(gid0 + c) * 3 + 1];
        cz[c] = g_centers[(gid0 + c) * 3 + 2];
        cc2[c] = __fmaf_rn(cx[c], cx[c], __fmaf_rn(cy[c], cy[c], __fmul_rn(cz[c], cz[c])));
    }
    for (int i = tid; i < KNN_C * 2048; i += 256) hist[i] = 0;
    __syncthreads();

    for (int n = tid; n < N_; n += 256) {
        float4 q = g_xyz[b * N_ + n];
#pragma unroll
        for (int c = 0; c < KNN_C; c++) {
            float d2 = dist2c(cx[c], cy[c], cz[c], cc2[c], q);
            atomicAdd(&hist[c * 2048 + (okey(d2) >> 21)], 1);
        }
    }
    __syncthreads();

    for (int c = 0; c < KNN_C; c++) {
        int* hc = hist + c * 2048;
        int s = 0;
#pragma unroll
        for (int t = 0; t < 8; ++t) s += hc[tid * 8 + t];
        scansm[tid] = s;
        __syncthreads();
        for (int off = 1; off < 256; off <<= 1) {
            int v = (tid >= off) ? scansm[tid - off] : 0;
            __syncthreads();
            scansm[tid] += v;
            __syncthreads();
        }
        int excl = scansm[tid] - s;
        if (excl < K_ && excl + s >= K_) {
            int cum = excl;
#pragma unroll
            for (int t = 0; t < 8; ++t) {
                int cc = hc[tid * 8 + t];
                if (cum + cc >= K_) { selbin[c] = tid * 8 + t; break; }
                cum += cc;
            }
        }
        __syncthreads();
    }
    if (tid < KNN_C) { lessc[tid] = 0; candc[tid] = 0; }
    __syncthreads();

    for (int n = tid; n < N_; n += 256) {
        float4 q = g_xyz[b * N_ + n];
#pragma unroll
        for (int c = 0; c < KNN_C; c++) {
            float d2 = dist2c(cx[c], cy[c], cz[c], cc2[c], q);
            unsigned u = okey(d2);
            int bin = (int)(u >> 21);
            if (bin < selbin[c]) {
                int p = atomicAdd(&lessc[c], 1);
                g_gidx[(size_t)(gid0 + c) * K_ + p] = n;
            } else if (bin == selbin[c]) {
                int e = atomicAdd(&candc[c], 1);
                if (e < 1024) {
                    hist[c * 2048 + e] = n;
                    hist[c * 2048 + 1024 + e] = (int)u;
                }
            }
        }
    }
    __syncthreads();

    for (int c = 0; c < KNN_C; c++) {
        int less = lessc[c];
        int cnt = candc[c];
        int need = K_ - less;
        int* gout = g_gidx + (size_t)(gid0 + c) * K_;
        if (cnt <= 1024) {
            int* cl = hist + c * 2048;
            for (int i = tid; i < cnt; i += 256) {
                int ni = cl[i];
                unsigned ui = (unsigned)cl[1024 + i];
                int rnk = 0;
                for (int j = 0; j < cnt; ++j) {
                    unsigned uj = (unsigned)cl[1024 + j];
                    int nj = cl[j];
                    rnk += (uj < ui || (uj == ui && nj < ni)) ? 1 : 0;
                }
                if (rnk < need) gout[less + rnk] = ni;
            }
        } else if (tid == 0) {
            int cc = 0;
            for (int n = 0; n < N_ && cc < need; ++n) {
                float4 q = g_xyz[b * N_ + n];
                float d2 = dist2c(cx[c], cy[c], cz[c], cc2[c], q);
                if ((int)(okey(d2) >> 21) == selbin[c]) { gout[less + cc] = n; ++cc; }
            }
        }
    }
}

// -------------------- mma.sync tf32 encoder (R13 2-group version) ---------------
template<int KT, int NPH, int NPT, int SIN, int SOUT>
__device__ __forceinline__ void mma_layer_bn(
    const uint32_t* __restrict__ As, uint32_t* __restrict__ Ds,
    const uint32_t* __restrict__ wf, int p0,
    const float* __restrict__ ps, const float* __restrict__ po,
    int warp, int lane)
{
    float acc[2 * NPH][4];
#pragma unroll
    for (int t = 0; t < 2 * NPH; t++)
#pragma unroll
        for (int q = 0; q < 4; q++) acc[t][q] = 0.0f;
    const int g = lane >> 2, tig = lane & 3;
    const int row = warp * 16 + g;
#pragma unroll 2
    for (int kt = 0; kt < KT; kt++) {
        const uint32_t* ap = As + row * SIN + kt * 8 + tig;
        uint32_t a0 = ap[0], a2 = ap[4];
        uint32_t a1 = ap[8 * SIN], a3 = ap[8 * SIN + 4];
        const uint4* wp = (const uint4*)wf + ((size_t)(kt * NPT + p0)) * 32 + lane;
#pragma unroll
        for (int pp = 0; pp < NPH; pp++) {
            uint4 W = __ldg(wp + pp * 32);
            mma_tf32(acc[2 * pp],     a0, a1, a2, a3, W.x, W.y);
            mma_tf32(acc[2 * pp + 1], a0, a1, a2, a3, W.z, W.w);
        }
    }
#pragma unroll
    for (int t = 0; t < 2 * NPH; t++) {
        int j0 = (p0 * 2 + t) * 8 + 2 * tig;
        float s0 = __ldg(ps + j0), s1 = __ldg(ps + j0 + 1);
        float q0 = __ldg(po + j0), q1 = __ldg(po + j0 + 1);
        uint32_t* d0 = Ds + row * SOUT + j0;
        uint32_t* d1 = Ds + (row + 8) * SOUT + j0;
        d0[0] = f2tf32(fmaxf(fmaf(acc[t][0], s0, q0), 0.0f));
        d0[1] = f2tf32(fmaxf(fmaf(acc[t][1], s1, q1), 0.0f));
        d1[0] = f2tf32(fmaxf(fmaf(acc[t][2], s0, q0), 0.0f));
        d1[1] = f2tf32(fmaxf(fmaf(acc[t][3], s1, q1), 0.0f));
    }
}

template<int KT, int NPH, int NPT, int SIN>
__device__ __forceinline__ void mma_layer_max(
    const uint32_t* __restrict__ As, const uint32_t* __restrict__ wf, int p0,
    float* __restrict__ maxw, int warp, int lane)
{
    float acc[2 * NPH][4];
#pragma unroll
    for (int t = 0; t < 2 * NPH; t++)
#pragma unroll
        for (int q = 0; q < 4; q++) acc[t][q] = 0.0f;
    const int g = lane >> 2, tig = lane & 3;
    const int row = warp * 16 + g;
#pragma unroll 2
    for (int kt = 0; kt < KT; kt++) {
        const uint32_t* ap = As + row * SIN + kt * 8 + tig;
        uint32_t a0 = ap[0], a2 = ap[4];
        uint32_t a1 = ap[8 * SIN], a3 = ap[8 * SIN + 4];
        const uint4* wp = (const uint4*)wf + ((size_t)(kt * NPT + p0)) * 32 + lane;
#pragma unroll
        for (int pp = 0; pp < NPH; pp++) {
            uint4 W = __ldg(wp + pp * 32);
            mma_tf32(acc[2 * pp],     a0, a1, a2, a3, W.x, W.y);
            mma_tf32(acc[2 * pp + 1], a0, a1, a2, a3, W.z, W.w);
        }
    }
#pragma unroll
    for (int t = 0; t < 2 * NPH; t++) {
        int j0 = (p0 * 2 + t) * 8 + 2 * tig;
        float m0 = fmaxf(acc[t][0], acc[t][2]);
        float m1 = fmaxf(acc[t][1], acc[t][3]);
#pragma unroll
        for (int o = 4; o < 32; o <<= 1) {
            m0 = fmaxf(m0, __shfl_xor_sync(0xffffffffu, m0, o));
            m1 = fmaxf(m1, __shfl_xor_sync(0xffffffffu, m1, o));
        }
        if (g == 0) {
            maxw[warp * 392 + j0] = m0;
            maxw[warp * 392 + j0 + 1] = m1;
        }
    }
}

__global__ void __launch_bounds__(128, 2) encoder_kernel(
    const float* __restrict__ pts, const float* __restrict__ b4,
    float* __restrict__ tokens)
{
    extern __shared__ uint32_t esm[];
    uint32_t* X = esm;
    uint32_t* Y = esm + 16640;
    float* maxw = (float*)Y;

    const int tid = threadIdx.x;
    const int warp = tid >> 5, lane = tid & 31;

    if (tid < 64) {
        int gid2 = blockIdx.x * 2 + (tid >> 5);
        int b = gid2 >> 9;
        int n = g_gidx[(size_t)gid2 * K_ + (tid & 31)];
        const float* p = pts + (size_t)(b * N_ + n) * C_;
        float cx = g_centers[gid2 * 3 + 0];
        float cy = g_centers[gid2 * 3 + 1];
        float cz = g_centers[gid2 * 3 + 2];
        float x = p[0], y = p[1], z = p[2];
        uint32_t* r = Y + tid * 36;
        r[0] = f2tf32(x - cx); r[1] = f2tf32(y - cy); r[2] = f2tf32(z - cz);
        r[3] = f2tf32(x); r[4] = f2tf32(y); r[5] = f2tf32(z);
        r[6] = f2tf32(p[3]); r[7] = f2tf32(p[4]); r[8] = f2tf32(p[5]);
#pragma unroll
        for (int c = 9; c < 16; c++) r[c] = 0u;
    }
    __syncthreads();

    mma_layer_bn<2, 4, 4, 36, 68>(Y, X, g_wf1, 0, g_ps, g_po, warp, lane);
    __syncwarp();
    mma_layer_bn<8, 8, 8, 68, 132>(X, Y, g_wf2, 0, g_ps + 64, g_po + 64, warp, lane);
    __syncwarp();
    mma_layer_bn<16, 8, 16, 132, 260>(Y, X, g_wf3, 0, g_ps + 192, g_po + 192, warp, lane);
    mma_layer_bn<16, 8, 16, 132, 260>(Y, X, g_wf3, 8, g_ps + 192, g_po + 192, warp, lane);
    __syncwarp();
    __syncthreads();
    mma_layer_max<32, 12, 24, 260>(X, g_wf4, 0,  maxw, warp, lane);
    mma_layer_max<32, 12, 24, 260>(X, g_wf4, 12, maxw, warp, lane);
    __syncthreads();

    for (int i = tid; i < 768; i += 128) {
        int g = i / 384, col = i - g * 384;
        float mx = fmaxf(maxw[(2 * g) * 392 + col], maxw[(2 * g + 1) * 392 + col]);
        tokens[(size_t)(blockIdx.x * 2 + g) * 384 + col] = mx + __ldg(b4 + col);
    }
}

// -------------------- positional MLP: 8 centers/CTA --------------------
__global__ void __launch_bounds__(384) pos_kernel(
    const float* __restrict__ pw1, const float* __restrict__ pb1,
    const float* __restrict__ pw2, const float* __restrict__ pb2,
    float* __restrict__ tokens)
{
    __shared__ float h[8 * 128];
    const int gid0 = blockIdx.x * 8;
    const int tid = threadIdx.x;

    for (int idx = tid; idx < 8 * 128; idx += 384) {
        int c = idx >> 7, col = idx & 127;
        float cx = g_centers[(gid0 + c) * 3 + 0];
        float cy = g_centers[(gid0 + c) * 3 + 1];
        float cz = g_centers[(gid0 + c) * 3 + 2];
        float t = cx * __ldg(pw1 + col) + cy * __ldg(pw1 + 128 + col)
                + cz * __ldg(pw1 + 256 + col) + __ldg(pb1 + col);
        h[idx] = 0.5f * t * (1.0f + erff(t * 0.70710678118654752f));
    }
    __syncthreads();

    const int col = tid;
    float acc[8];
    float bj = __ldg(pb2 + col);
#pragma unroll
    for (int c = 0; c < 8; c++) acc[c] = bj;
#pragma unroll 2
    for (int k = 0; k < 128; ++k) {
        float w = __ldg(pw2 + (size_t)k * 384 + col);
#pragma unroll
        for (int c = 0; c < 8; c++)
            acc[c] = fmaf(h[c * 128 + k], w, acc[c]);
    }
#pragma unroll
    for (int c = 0; c < 8; c++)
        tokens[(size_t)(gid0 + c) * 384 + col] += acc[c];
}

// -------------------- launch --------------------
extern "C" void kernel_launch(void* const* d_in, const int* in_sizes, int n_in,
                              void* d_out, int out_size)
{
    const float* pts = (const float*)d_in[0];
    const float* w1 = (const float*)d_in[1],  *b1 = (const float*)d_in[2];
    const float* g1 = (const float*)d_in[3],  *be1 = (const float*)d_in[4];
    const float* m1 = (const float*)d_in[5],  *v1 = (const float*)d_in[6];
    const float* w2 = (const float*)d_in[7],  *b2 = (const float*)d_in[8];
    const float* g2 = (const float*)d_in[9],  *be2 = (const float*)d_in[10];
    const float* m2 = (const float*)d_in[11], *v2 = (const float*)d_in[12];
    const float* w3 = (const float*)d_in[13], *b3 = (const float*)d_in[14];
    const float* g3 = (const float*)d_in[15], *be3 = (const float*)d_in[16];
    const float* m3 = (const float*)d_in[17], *v3 = (const float*)d_in[18];
    const float* w4 = (const float*)d_in[19], *b4 = (const float*)d_in[20];
    const float* pw1 = (const float*)d_in[21], *pb1 = (const float*)d_in[22];
    const float* pw2 = (const float*)d_in[23], *pb2 = (const float*)d_in[24];

    float* out = (float*)d_out;
    float* tokens = out;
    float* centers_out =
        (out_size >= B_ * M_ * 384 + B_ * M_ * 3) ? (out + (size_t)B_ * M_ * 384)
                                                  : nullptr;

    const int FPS_SMEM = (24704 + 96) * 4;    // 99,200 B
    const int ENC_SMEM = (16640 + 8448) * 4;  // 100,352 B

    cudaFuncSetAttribute(fps_kernel, cudaFuncAttributeMaxDynamicSharedMemorySize, FPS_SMEM);
    cudaFuncSetAttribute(encoder_kernel, cudaFuncAttributeMaxDynamicSharedMemorySize, ENC_SMEM);

    const int TOT = T1 + T2 + T3 + T4;
    prep_frag_all<<<(TOT + 255) / 256, 256>>>(w1, w2, w3, w4);
    prep_p_all<<<2, 256>>>(b1, g1, be1, m1, v1, b2, g2, be2, m2, v2, b3, g3, be3, m3, v3);
    pack_kernel<<<(B_ * N_ + 255) / 256, 256>>>(pts);
    fps_kernel<<<B_ * 2, 1024, FPS_SMEM>>>(centers_out);
    knn_kernel<<<B_ * M_ / KNN_C, 256>>>();
    encoder_kernel<<<B_ * M_ / 2, 128, ENC_SMEM>>>(pts, b4, tokens);
    pos_kernel<<<B_ * M_ / 8, 384>>>(pw1, pb1, pw2, pb2, tokens);
}

// round 16
// speedup vs baseline: 1.3177x; 1.3177x over previous
#include <cuda_runtime.h>
#include <math.h>
#include <stdint.h>

#define B_ 8
#define N_ 16384
#define M_ 512
#define K_ 32
#define C_ 6
#define FPS_P 4096      // points per FPS CTA (4-CTA cluster)

// -------------------- scratch --------------------
__device__ int    g_center_idx[B_ * M_];
__device__ float  g_centers[B_ * M_ * 3];
__device__ int    g_gidx[B_ * M_ * K_];
__device__ float4 g_xyz[B_ * N_];
__device__ __align__(16) uint32_t g_wf1[2 * 4 * 128];
__device__ __align__(16) uint32_t g_wf2[8 * 8 * 128];
__device__ __align__(16) uint32_t g_wf3[16 * 16 * 128];
__device__ __align__(16) uint32_t g_wf4[32 * 24 * 128];
__device__ float g_ps[448], g_po[448];

// -------------------- helpers --------------------
__device__ __forceinline__ unsigned okey(float f) {
    unsigned u = __float_as_uint(f);
    unsigned mask = (u & 0x80000000u) ? 0xFFFFFFFFu : 0x80000000u;
    return u ^ mask;
}
__device__ __forceinline__ uint32_t f2tf32(float x) {
    uint32_t r;
    asm("cvt.rna.tf32.f32 %0, %1;" : "=r"(r) : "f"(x));
    return r;
}
__device__ __forceinline__ void mma_tf32(float* c, uint32_t a0, uint32_t a1,
                                         uint32_t a2, uint32_t a3,
                                         uint32_t b0, uint32_t b1) {
    asm volatile(
        "mma.sync.aligned.m16n8k8.row.col.f32.tf32.tf32.f32 "
        "{%0,%1,%2,%3}, {%4,%5,%6,%7}, {%8,%9}, {%0,%1,%2,%3};"
        : "+f"(c[0]), "+f"(c[1]), "+f"(c[2]), "+f"(c[3])
        : "r"(a0), "r"(a1), "r"(a2), "r"(a3), "r"(b0), "r"(b1));
}
__device__ __forceinline__ uint32_t smem_u32(const void* p) {
    uint32_t a;
    asm("{ .reg .u64 t; cvta.to.shared.u64 t, %1; cvt.u32.u64 %0, t; }" : "=r"(a) : "l"(p));
    return a;
}
__device__ __forceinline__ uint32_t mapa_sh(uint32_t addr, uint32_t rank) {
    uint32_t r;
    asm("mapa.shared::cluster.u32 %0, %1, %2;" : "=r"(r) : "r"(addr), "r"(rank));
    return r;
}
__device__ __forceinline__ void stsc_u64(uint32_t a, unsigned long long v) {
    asm volatile("st.shared::cluster.b64 [%0], %1;" :: "r"(a), "l"(v) : "memory");
}
__device__ __forceinline__ void stsc_u32(uint32_t a, unsigned v) {
    asm volatile("st.shared::cluster.b32 [%0], %1;" :: "r"(a), "r"(v) : "memory");
}
__device__ __forceinline__ void cluster_sync_() {
    asm volatile("barrier.cluster.arrive.aligned;" ::: "memory");
    asm volatile("barrier.cluster.wait.aligned;" ::: "memory");
}
__device__ __forceinline__ unsigned long long packu64(unsigned lo, unsigned hi) {
    unsigned long long d;
    asm("mov.b64 %0, {%1, %2};" : "=l"(d) : "r"(lo), "r"(hi));
    return d;
}
__device__ __forceinline__ float dist2c(float cx, float cy, float cz, float cc2,
                                        float4 q) {
    float dot = __fmaf_rn(cx, q.x, __fmaf_rn(cy, q.y, __fmul_rn(cz, q.z)));
    return __fadd_rn(__fmaf_rn(-2.0f, dot, cc2), q.w);
}

// -------------------- merged weight-fragment prep --------------------
__device__ __forceinline__ void frag_one(const float* w, uint32_t* dst,
                                         int CIN, int DOUT, int idx) {
    int r = idx & 1, o = (idx >> 1) & 1, lane = (idx >> 2) & 31;
    int rest = idx >> 7;
    int np = DOUT / 16;
    int p = rest % np, kt = rest / np;
    int nt = 2 * p + o;
    int n = nt * 8 + (lane >> 2);
    int k = kt * 8 + (lane & 3) + 4 * r;
    float v = (k < CIN) ? w[(size_t)k * DOUT + n] : 0.0f;
    dst[idx] = f2tf32(v);
}
#define T1 (2 * 4 * 128)
#define T2 (8 * 8 * 128)
#define T3 (16 * 16 * 128)
#define T4 (32 * 24 * 128)
__global__ void prep_frag_all(const float* __restrict__ w1, const float* __restrict__ w2,
                              const float* __restrict__ w3, const float* __restrict__ w4) {
    int idx = blockIdx.x * blockDim.x + threadIdx.x;
    if (idx < T1) { frag_one(w1, g_wf1, 9, 64, idx); return; }
    idx -= T1;
    if (idx < T2) { frag_one(w2, g_wf2, 64, 128, idx); return; }
    idx -= T2;
    if (idx < T3) { frag_one(w3, g_wf3, 128, 256, idx); return; }
    idx -= T3;
    if (idx < T4) { frag_one(w4, g_wf4, 256, 384, idx); }
}

__global__ void prep_p_all(
    const float* __restrict__ b1, const float* __restrict__ g1,
    const float* __restrict__ be1, const float* __restrict__ m1, const float* __restrict__ v1,
    const float* __restrict__ b2, const float* __restrict__ g2,
    const float* __restrict__ be2, const float* __restrict__ m2, const float* __restrict__ v2,
    const float* __restrict__ b3, const float* __restrict__ g3,
    const float* __restrict__ be3, const float* __restrict__ m3, const float* __restrict__ v3)
{
    int i = blockIdx.x * blockDim.x + threadIdx.x;
    if (i >= 448) return;
    const float *b, *g, *be, *m, *v;
    int off;
    if (i < 64)       { b = b1; g = g1; be = be1; m = m1; v = v1; off = i; }
    else if (i < 192) { b = b2; g = g2; be = be2; m = m2; v = v2; off = i - 64; }
    else              { b = b3; g = g3; be = be3; m = m3; v = v3; off = i - 192; }
    float sc = g[off] * rsqrtf(v[off] + 1e-5f);
    g_ps[i] = sc;
    g_po[i] = (b[off] - m[off]) * sc + be[off];
}

// -------------------- pack xyz --------------------
__global__ void pack_kernel(const float* __restrict__ pts) {
    int i = blockIdx.x * blockDim.x + threadIdx.x;
    if (i < B_ * N_) {
        const float* p = pts + (size_t)i * C_;
        float x = p[0], y = p[1], z = p[2];
        g_xyz[i] = make_float4(x, y, z, x * x + y * y + z * z);
    }
}

// -------------------- FPS: 4-CTA cluster, register-resident scan (R14) ----------
// smem: sq float4[4096] | rk[32] ri[32] @16384 floats | mail u32[2][4][6] @16448
__global__ void __launch_bounds__(1024, 1) __cluster_dims__(4, 1, 1)
fps_kernel(float* centers_out) {
    extern __shared__ float fsm[];
    float4*   sq = (float4*)fsm;
    unsigned* rk = (unsigned*)(fsm + 16384);
    unsigned* ri = rk + 32;
    unsigned* mail = (unsigned*)(fsm + 16448);   // 2 buffers x 4 records x 6 u32
    const float* mailf = (const float*)mail;

    const int b = blockIdx.x >> 2;
    const uint32_t rank = blockIdx.x & 3;
    const int tid = threadIdx.x;
    const int lane = tid & 31, wid = tid >> 5;
    const uint32_t mail_b = smem_u32(mail);

    // stage points to SMEM (for winner lookup) and registers (for the scan)
    float px[4], py[4], pz[4];
#pragma unroll
    for (int j = 0; j < 4; j++) {
        int n = j * 1024 + tid;
        float4 q = g_xyz[b * N_ + rank * FPS_P + n];
        sq[n] = q;
        px[j] = q.x; py[j] = q.y; pz[j] = q.z;
    }
    float dist[4];
#pragma unroll
    for (int j = 0; j < 4; j++) dist[j] = 1e10f;
    __syncthreads();

    if (rank == 0 && tid == 0) {
        float4 q = sq[0];
        for (uint32_t r = 0; r < 4; r++) {
            uint32_t a = mapa_sh(mail_b + 96, r);   // buffer 1, record 0
            stsc_u64(a + 8, packu64(__float_as_uint(q.x), __float_as_uint(q.y)));
            stsc_u32(a + 16, __float_as_uint(q.z));
        }
    }
    cluster_sync_();
    int far = 0;
    float cx = mailf[24 + 2], cy = mailf[24 + 3], cz = mailf[24 + 4];

    for (int it = 0; it < M_; ++it) {
        if (rank == 0 && tid == 0) {
            g_center_idx[b * M_ + it] = far;
            float* gc = g_centers + (size_t)(b * M_ + it) * 3;
            gc[0] = cx; gc[1] = cy; gc[2] = cz;
            if (centers_out) {
                float* oc = centers_out + (size_t)(b * M_ + it) * 3;
                oc[0] = cx; oc[1] = cy; oc[2] = cz;
            }
        }
        float bd = -1.0f; int bi = 0x7fffffff;
#pragma unroll
        for (int j = 0; j < 4; j++) {
            float dx = px[j] - cx, dy = py[j] - cy, dz = pz[j] - cz;
            float d = dx * dx + dy * dy + dz * dz;
            float nd = fminf(dist[j], d);
            dist[j] = nd;
            if (nd > bd) { bd = nd; bi = j * 1024 + tid; }
        }
        unsigned key = okey(bd);
        unsigned kmax = __reduce_max_sync(0xffffffffu, key);
        unsigned cnd = (key == kmax) ? (unsigned)bi : 0xffffffffu;
        unsigned imin = __reduce_min_sync(0xffffffffu, cnd);
        if (lane == 0) { rk[wid] = kmax; ri[wid] = imin; }
        __syncthreads();
        const int p = it & 1;
        if (wid == 0) {
            unsigned k2 = rk[lane], i2 = ri[lane];
            unsigned kmax2 = __reduce_max_sync(0xffffffffu, k2);
            unsigned cnd2 = (k2 == kmax2) ? i2 : 0xffffffffu;
            unsigned imin2 = __reduce_min_sync(0xffffffffu, cnd2);
            if (lane < 4) {   // redux broadcasts: lanes 0..3 ship record to rank=lane
                int li = (int)imin2;
                unsigned gi = rank * FPS_P + (unsigned)li;
                float4 q = sq[li];
                uint32_t a = mapa_sh(mail_b + p * 96 + rank * 24, (uint32_t)lane);
                stsc_u64(a, packu64(kmax2, gi));
                stsc_u64(a + 8, packu64(__float_as_uint(q.x), __float_as_uint(q.y)));
                stsc_u32(a + 16, __float_as_uint(q.z));
            }
        }
        cluster_sync_();
        const unsigned* mb = mail + p * 24;
        unsigned wkey = mb[0]; unsigned wi = mb[1]; int ws = 0;
#pragma unroll
        for (int s = 1; s < 4; s++) {
            unsigned k = mb[s * 6]; unsigned i = mb[s * 6 + 1];
            if (k > wkey || (k == wkey && i < wi)) { wkey = k; wi = i; ws = s; }
        }
        cx = __uint_as_float(mb[ws * 6 + 2]);
        cy = __uint_as_float(mb[ws * 6 + 3]);
        cz = __uint_as_float(mb[ws * 6 + 4]);
        far = (int)wi;
    }
}

// -------------------- kNN: 4 centers/CTA, recompute-d2 --------------------
#define KNN_C 4
__global__ void __launch_bounds__(256) knn_kernel() {
    __shared__ int hist[KNN_C * 2048];
    __shared__ int scansm[256];
    __shared__ int selbin[KNN_C], lessc[KNN_C], candc[KNN_C];

    const int bid = blockIdx.x;
    const int gid0 = bid * KNN_C;
    const int b = gid0 >> 9;
    const int tid = threadIdx.x;

    float cx[KNN_C], cy[KNN_C], cz[KNN_C], cc2[KNN_C];
#pragma unroll
    for (int c = 0; c < KNN_C; c++) {
        cx[c] = g_centers[(gid0 + c) * 3 + 0];
        cy[c] = g_centers[(gid0 + c) * 3 + 1];
        cz[c] = g_centers[(gid0 + c) * 3 + 2];
        cc2[c] = __fmaf_rn(cx[c], cx[c], __fmaf_rn(cy[c], cy[c], __fmul_rn(cz[c], cz[c])));
    }
    for (int i = tid; i < KNN_C * 2048; i += 256) hist[i] = 0;
    __syncthreads();

    for (int n = tid; n < N_; n += 256) {
        float4 q = g_xyz[b * N_ + n];
#pragma unroll
        for (int c = 0; c < KNN_C; c++) {
            float d2 = dist2c(cx[c], cy[c], cz[c], cc2[c], q);
            atomicAdd(&hist[c * 2048 + (okey(d2) >> 21)], 1);
        }
    }
    __syncthreads();

    for (int c = 0; c < KNN_C; c++) {
        int* hc = hist + c * 2048;
        int s = 0;
#pragma unroll
        for (int t = 0; t < 8; ++t) s += hc[tid * 8 + t];
        scansm[tid] = s;
        __syncthreads();
        for (int off = 1; off < 256; off <<= 1) {
            int v = (tid >= off) ? scansm[tid - off] : 0;
            __syncthreads();
            scansm[tid] += v;
            __syncthreads();
        }
        int excl = scansm[tid] - s;
        if (excl < K_ && excl + s >= K_) {
            int cum = excl;
#pragma unroll
            for (int t = 0; t < 8; ++t) {
                int cc = hc[tid * 8 + t];
                if (cum + cc >= K_) { selbin[c] = tid * 8 + t; break; }
                cum += cc;
            }
        }
        __syncthreads();
    }
    if (tid < KNN_C) { lessc[tid] = 0; candc[tid] = 0; }
    __syncthreads();

    for (int n = tid; n < N_; n += 256) {
        float4 q = g_xyz[b * N_ + n];
#pragma unroll
        for (int c = 0; c < KNN_C; c++) {
            float d2 = dist2c(cx[c], cy[c], cz[c], cc2[c], q);
            unsigned u = okey(d2);
            int bin = (int)(u >> 21);
            if (bin < selbin[c]) {
                int p = atomicAdd(&lessc[c], 1);
                g_gidx[(size_t)(gid0 + c) * K_ + p] = n;
            } else if (bin == selbin[c]) {
                int e = atomicAdd(&candc[c], 1);
                if (e < 1024) {
                    hist[c * 2048 + e] = n;
                    hist[c * 2048 + 1024 + e] = (int)u;
                }
            }
        }
    }
    __syncthreads();

    for (int c = 0; c < KNN_C; c++) {
        int less = lessc[c];
        int cnt = candc[c];
        int need = K_ - less;
        int* gout = g_gidx + (size_t)(gid0 + c) * K_;
        if (cnt <= 1024) {
            int* cl = hist + c * 2048;
            for (int i = tid; i < cnt; i += 256) {
                int ni = cl[i];
                unsigned ui = (unsigned)cl[1024 + i];
                int rnk = 0;
                for (int j = 0; j < cnt; ++j) {
                    unsigned uj = (unsigned)cl[1024 + j];
                    int nj = cl[j];
                    rnk += (uj < ui || (uj == ui && nj < ni)) ? 1 : 0;
                }
                if (rnk < need) gout[less + rnk] = ni;
            }
        } else if (tid == 0) {
            int cc = 0;
            for (int n = 0; n < N_ && cc < need; ++n) {
                float4 q = g_xyz[b * N_ + n];
                float d2 = dist2c(cx[c], cy[c], cz[c], cc2[c], q);
                if ((int)(okey(d2) >> 21) == selbin[c]) { gout[less + cc] = n; ++cc; }
            }
        }
    }
}

// -------------------- mma.sync tf32 encoder (R13 2-group version) ---------------
template<int KT, int NPH, int NPT, int SIN, int SOUT>
__device__ __forceinline__ void mma_layer_bn(
    const uint32_t* __restrict__ As, uint32_t* __restrict__ Ds,
    const uint32_t* __restrict__ wf, int p0,
    const float* __restrict__ ps, const float* __restrict__ po,
    int warp, int lane)
{
    float acc[2 * NPH][4];
#pragma unroll
    for (int t = 0; t < 2 * NPH; t++)
#pragma unroll
        for (int q = 0; q < 4; q++) acc[t][q] = 0.0f;
    const int g = lane >> 2, tig = lane & 3;
    const int row = warp * 16 + g;
#pragma unroll 2
    for (int kt = 0; kt < KT; kt++) {
        const uint32_t* ap = As + row * SIN + kt * 8 + tig;
        uint32_t a0 = ap[0], a2 = ap[4];
        uint32_t a1 = ap[8 * SIN], a3 = ap[8 * SIN + 4];
        const uint4* wp = (const uint4*)wf + ((size_t)(kt * NPT + p0)) * 32 + lane;
#pragma unroll
        for (int pp = 0; pp < NPH; pp++) {
            uint4 W = __ldg(wp + pp * 32);
            mma_tf32(acc[2 * pp],     a0, a1, a2, a3, W.x, W.y);
            mma_tf32(acc[2 * pp + 1], a0, a1, a2, a3, W.z, W.w);
        }
    }
#pragma unroll
    for (int t = 0; t < 2 * NPH; t++) {
        int j0 = (p0 * 2 + t) * 8 + 2 * tig;
        float s0 = __ldg(ps + j0), s1 = __ldg(ps + j0 + 1);
        float q0 = __ldg(po + j0), q1 = __ldg(po + j0 + 1);
        uint32_t* d0 = Ds + row * SOUT + j0;
        uint32_t* d1 = Ds + (row + 8) * SOUT + j0;
        d0[0] = f2tf32(fmaxf(fmaf(acc[t][0], s0, q0), 0.0f));
        d0[1] = f2tf32(fmaxf(fmaf(acc[t][1], s1, q1), 0.0f));
        d1[0] = f2tf32(fmaxf(fmaf(acc[t][2], s0, q0), 0.0f));
        d1[1] = f2tf32(fmaxf(fmaf(acc[t][3], s1, q1), 0.0f));
    }
}

template<int KT, int NPH, int NPT, int SIN>
__device__ __forceinline__ void mma_layer_max(
    const uint32_t* __restrict__ As, const uint32_t* __restrict__ wf, int p0,
    float* __restrict__ maxw, int warp, int lane)
{
    float acc[2 * NPH][4];
#pragma unroll
    for (int t = 0; t < 2 * NPH; t++)
#pragma unroll
        for (int q = 0; q < 4; q++) acc[t][q] = 0.0f;
    const int g = lane >> 2, tig = lane & 3;
    const int row = warp * 16 + g;
#pragma unroll 2
    for (int kt = 0; kt < KT; kt++) {
        const uint32_t* ap = As + row * SIN + kt * 8 + tig;
        uint32_t a0 = ap[0], a2 = ap[4];
        uint32_t a1 = ap[8 * SIN], a3 = ap[8 * SIN + 4];
        const uint4* wp = (const uint4*)wf + ((size_t)(kt * NPT + p0)) * 32 + lane;
#pragma unroll
        for (int pp = 0; pp < NPH; pp++) {
            uint4 W = __ldg(wp + pp * 32);
            mma_tf32(acc[2 * pp],     a0, a1, a2, a3, W.x, W.y);
            mma_tf32(acc[2 * pp + 1], a0, a1, a2, a3, W.z, W.w);
        }
    }
#pragma unroll
    for (int t = 0; t < 2 * NPH; t++) {
        int j0 = (p0 * 2 + t) * 8 + 2 * tig;
        float m0 = fmaxf(acc[t][0], acc[t][2]);
        float m1 = fmaxf(acc[t][1], acc[t][3]);
#pragma unroll
        for (int o = 4; o < 32; o <<= 1) {
            m0 = fmaxf(m0, __shfl_xor_sync(0xffffffffu, m0, o));
            m1 = fmaxf(m1, __shfl_xor_sync(0xffffffffu, m1, o));
        }
        if (g == 0) {
            maxw[warp * 392 + j0] = m0;
            maxw[warp * 392 + j0 + 1] = m1;
        }
    }
}

__global__ void __launch_bounds__(128, 2) encoder_kernel(
    const float* __restrict__ pts, const float* __restrict__ b4,
    float* __restrict__ tokens)
{
    extern __shared__ uint32_t esm[];
    uint32_t* X = esm;
    uint32_t* Y = esm + 16640;
    float* maxw = (float*)Y;

    const int tid = threadIdx.x;
    const int warp = tid >> 5, lane = tid & 31;

    if (tid < 64) {
        int gid2 = blockIdx.x * 2 + (tid >> 5);
        int b = gid2 >> 9;
        int n = g_gidx[(size_t)gid2 * K_ + (tid & 31)];
        const float* p = pts + (size_t)(b * N_ + n) * C_;
        float cx = g_centers[gid2 * 3 + 0];
        float cy = g_centers[gid2 * 3 + 1];
        float cz = g_centers[gid2 * 3 + 2];
        float x = p[0], y = p[1], z = p[2];
        uint32_t* r = Y + tid * 36;
        r[0] = f2tf32(x - cx); r[1] = f2tf32(y - cy); r[2] = f2tf32(z - cz);
        r[3] = f2tf32(x); r[4] = f2tf32(y); r[5] = f2tf32(z);
        r[6] = f2tf32(p[3]); r[7] = f2tf32(p[4]); r[8] = f2tf32(p[5]);
#pragma unroll
        for (int c = 9; c < 16; c++) r[c] = 0u;
    }
    __syncthreads();

    mma_layer_bn<2, 4, 4, 36, 68>(Y, X, g_wf1, 0, g_ps, g_po, warp, lane);
    __syncwarp();
    mma_layer_bn<8, 8, 8, 68, 132>(X, Y, g_wf2, 0, g_ps + 64, g_po + 64, warp, lane);
    __syncwarp();
    mma_layer_bn<16, 8, 16, 132, 260>(Y, X, g_wf3, 0, g_ps + 192, g_po + 192, warp, lane);
    mma_layer_bn<16, 8, 16, 132, 260>(Y, X, g_wf3, 8, g_ps + 192, g_po + 192, warp, lane);
    __syncwarp();
    __syncthreads();
    mma_layer_max<32, 12, 24, 260>(X, g_wf4, 0,  maxw, warp, lane);
    mma_layer_max<32, 12, 24, 260>(X, g_wf4, 12, maxw, warp, lane);
    __syncthreads();

    for (int i = tid; i < 768; i += 128) {
        int g = i / 384, col = i - g * 384;
        float mx = fmaxf(maxw[(2 * g) * 392 + col], maxw[(2 * g + 1) * 392 + col]);
        tokens[(size_t)(blockIdx.x * 2 + g) * 384 + col] = mx + __ldg(b4 + col);
    }
}

// -------------------- positional MLP: 8 centers/CTA --------------------
__global__ void __launch_bounds__(384) pos_kernel(
    const float* __restrict__ pw1, const float* __restrict__ pb1,
    const float* __restrict__ pw2, const float* __restrict__ pb2,
    float* __restrict__ tokens)
{
    __shared__ float h[8 * 128];
    const int gid0 = blockIdx.x * 8;
    const int tid = threadIdx.x;

    for (int idx = tid; idx < 8 * 128; idx += 384) {
        int c = idx >> 7, col = idx & 127;
        float cx = g_centers[(gid0 + c) * 3 + 0];
        float cy = g_centers[(gid0 + c) * 3 + 1];
        float cz = g_centers[(gid0 + c) * 3 + 2];
        float t = cx * __ldg(pw1 + col) + cy * __ldg(pw1 + 128 + col)
                + cz * __ldg(pw1 + 256 + col) + __ldg(pb1 + col);
        h[idx] = 0.5f * t * (1.0f + erff(t * 0.70710678118654752f));
    }
    __syncthreads();

    const int col = tid;
    float acc[8];
    float bj = __ldg(pb2 + col);
#pragma unroll
    for (int c = 0; c < 8; c++) acc[c] = bj;
#pragma unroll 2
    for (int k = 0; k < 128; ++k) {
        float w = __ldg(pw2 + (size_t)k * 384 + col);
#pragma unroll
        for (int c = 0; c < 8; c++)
            acc[c] = fmaf(h[c * 128 + k], w, acc[c]);
    }
#pragma unroll
    for (int c = 0; c < 8; c++)
        tokens[(size_t)(gid0 + c) * 384 + col] += acc[c];
}

// -------------------- launch --------------------
extern "C" void kernel_launch(void* const* d_in, const int* in_sizes, int n_in,
                              void* d_out, int out_size)
{
    const float* pts = (const float*)d_in[0];
    const float* w1 = (const float*)d_in[1],  *b1 = (const float*)d_in[2];
    const float* g1 = (const float*)d_in[3],  *be1 = (const float*)d_in[4];
    const float* m1 = (const float*)d_in[5],  *v1 = (const float*)d_in[6];
    const float* w2 = (const float*)d_in[7],  *b2 = (const float*)d_in[8];
    const float* g2 = (const float*)d_in[9],  *be2 = (const float*)d_in[10];
    const float* m2 = (const float*)d_in[11], *v2 = (const float*)d_in[12];
    const float* w3 = (const float*)d_in[13], *b3 = (const float*)d_in[14];
    const float* g3 = (const float*)d_in[15], *be3 = (const float*)d_in[16];
    const float* m3 = (const float*)d_in[17], *v3 = (const float*)d_in[18];
    const float* w4 = (const float*)d_in[19], *b4 = (const float*)d_in[20];
    const float* pw1 = (const float*)d_in[21], *pb1 = (const float*)d_in[22];
    const float* pw2 = (const float*)d_in[23], *pb2 = (const float*)d_in[24];

    float* out = (float*)d_out;
    float* tokens = out;
    float* centers_out =
        (out_size >= B_ * M_ * 384 + B_ * M_ * 3) ? (out + (size_t)B_ * M_ * 384)
                                                  : nullptr;

    const int FPS_SMEM = (16448 + 48) * 4;    // 65,984 B
    const int ENC_SMEM = (16640 + 8448) * 4;  // 100,352 B

    cudaFuncSetAttribute(fps_kernel, cudaFuncAttributeMaxDynamicSharedMemorySize, FPS_SMEM);
    cudaFuncSetAttribute(encoder_kernel, cudaFuncAttributeMaxDynamicSharedMemorySize, ENC_SMEM);

    const int TOT = T1 + T2 + T3 + T4;
    prep_frag_all<<<(TOT + 255) / 256, 256>>>(w1, w2, w3, w4);
    prep_p_all<<<2, 256>>>(b1, g1, be1, m1, v1, b2, g2, be2, m2, v2, b3, g3, be3, m3, v3);
    pack_kernel<<<(B_ * N_ + 255) / 256, 256>>>(pts);
    fps_kernel<<<B_ * 4, 1024, FPS_SMEM>>>(centers_out);
    knn_kernel<<<B_ * M_ / KNN_C, 256>>>();
    encoder_kernel<<<B_ * M_ / 2, 128, ENC_SMEM>>>(pts, b4, tokens);
    pos_kernel<<<B_ * M_ / 8, 384>>>(pw1, pb1, pw2, pb2, tokens);
}